// round 2
// baseline (speedup 1.0000x reference)
#include <cuda_runtime.h>
#include <cstdint>

// RoiAlign (crop_and_resize, bilinear, extrapolation=0) with 2-level FPN select.
// feat0: [2,256,256,256] f32, feat1: [2,128,128,256] f32, rois: [2,512,5] f32
// out:   [2,512,7,7,256] f32
//
// Mapping: one 64-thread group handles one pooled cell (7x7 grid point) for
// all 256 channels via float4. 4 groups per 256-thread block.

#define NUM_B 2
#define NUM_R 512
#define CCH 256
#define POOL 7
#define CELLS_PER_BOX (POOL * POOL)
#define INV_IMG (1.0f / 1024.0f)
#define LVL_THRESH 48.0f

__global__ __launch_bounds__(256) void roialign_kernel(
    const float* __restrict__ feat0,
    const float* __restrict__ feat1,
    const float* __restrict__ rois,
    float* __restrict__ out,
    int n_cells)
{
    const int group = threadIdx.x >> 6;       // 0..3
    const int lane  = threadIdx.x & 63;       // 0..63, 4 channels each
    const int cell  = blockIdx.x * 4 + group;
    if (cell >= n_cells) return;

    const int box = cell / CELLS_PER_BOX;             // 0..1023
    const int pq  = cell - box * CELLS_PER_BOX;       // 0..48
    const int py  = pq / POOL;
    const int px  = pq - py * POOL;
    const int b   = box / NUM_R;                      // batch index

    const float* roi = rois + box * 5;
    const float y1 = roi[0];
    const float x1 = roi[1];
    const float y2 = roi[2];
    const float x2 = roi[3];

    const bool lvl1 = ((y2 - y1) > LVL_THRESH) || ((x2 - x1) > LVL_THRESH);
    const float* __restrict__ img = lvl1 ? feat1 : feat0;
    const int H = lvl1 ? 128 : 256;
    const int W = lvl1 ? 128 : 256;

    // normalized box coords (matches reference: boxes / 1024)
    const float y1n = y1 * INV_IMG, y2n = y2 * INV_IMG;
    const float x1n = x1 * INV_IMG, x2n = x2 * INV_IMG;

    const float ry = (float)py / 6.0f;
    const float rx = (float)px / 6.0f;
    const float ys = (y1n + ry * (y2n - y1n)) * (float)(H - 1);
    const float xs = (x1n + rx * (x2n - x1n)) * (float)(W - 1);

    float4* outp = reinterpret_cast<float4*>(out) + (size_t)cell * (CCH / 4) + lane;

    const bool valid = (ys >= 0.0f) && (ys <= (float)(H - 1)) &&
                       (xs >= 0.0f) && (xs <= (float)(W - 1));
    if (!valid) {
        *outp = make_float4(0.f, 0.f, 0.f, 0.f);
        return;
    }

    const float y0f = floorf(ys);
    const float x0f = floorf(xs);
    const float wy = ys - y0f;
    const float wx = xs - x0f;

    // clip in float, then cast (matches reference clip-then-astype)
    const float Hm1 = (float)(H - 1), Wm1 = (float)(W - 1);
    const int iy0 = (int)fminf(fmaxf(y0f,        0.f), Hm1);
    const int iyp = (int)fminf(fmaxf(y0f + 1.0f, 0.f), Hm1);
    const int ix0 = (int)fminf(fmaxf(x0f,        0.f), Wm1);
    const int ixp = (int)fminf(fmaxf(x0f + 1.0f, 0.f), Wm1);

    const size_t rowBase = ((size_t)b * H);
    const float4* __restrict__ img4 = reinterpret_cast<const float4*>(img);
    const size_t p00 = ((rowBase + iy0) * W + ix0) * (CCH / 4) + lane;
    const size_t p01 = ((rowBase + iy0) * W + ixp) * (CCH / 4) + lane;
    const size_t p10 = ((rowBase + iyp) * W + ix0) * (CCH / 4) + lane;
    const size_t p11 = ((rowBase + iyp) * W + ixp) * (CCH / 4) + lane;

    const float4 v00 = img4[p00];
    const float4 v01 = img4[p01];
    const float4 v10 = img4[p10];
    const float4 v11 = img4[p11];

    const float owx = 1.0f - wx;
    const float owy = 1.0f - wy;

    float4 r;
    {
        float top, bot;
        top = v00.x * owx + v01.x * wx;
        bot = v10.x * owx + v11.x * wx;
        r.x = top * owy + bot * wy;
        top = v00.y * owx + v01.y * wx;
        bot = v10.y * owx + v11.y * wx;
        r.y = top * owy + bot * wy;
        top = v00.z * owx + v01.z * wx;
        bot = v10.z * owx + v11.z * wx;
        r.z = top * owy + bot * wy;
        top = v00.w * owx + v01.w * wx;
        bot = v10.w * owx + v11.w * wx;
        r.w = top * owy + bot * wy;
    }
    *outp = r;
}

extern "C" void kernel_launch(void* const* d_in, const int* in_sizes, int n_in,
                              void* d_out, int out_size) {
    const float* feat0 = (const float*)d_in[0];
    const float* feat1 = (const float*)d_in[1];
    const float* rois  = (const float*)d_in[2];
    float* out = (float*)d_out;

    const int n_cells = NUM_B * NUM_R * CELLS_PER_BOX;   // 50176
    const int blocks = (n_cells + 3) / 4;                // 4 cells per 256-thread block
    roialign_kernel<<<blocks, 256>>>(feat0, feat1, rois, out, n_cells);
}